// round 1
// baseline (speedup 1.0000x reference)
#include <cuda_runtime.h>
#include <cuda_bf16.h>

#define NN   100000
#define EE   1000000
#define RR   4
#define GG   256
#define DHH  128
#define NCC  10
#define KK   (RR*DHH)   // 512

// ---------------- scratch (device globals; no allocation allowed) ----------------
__device__ float g_h0[(size_t)NN*DHH];          // 51.2 MB  ping
__device__ float g_h1[(size_t)NN*DHH];          // 51.2 MB  pong
__device__ float g_agg[(size_t)NN*KK];          // 204.8 MB concatenated per-relation aggregates
__device__ int   g_deg_out[RR*NN];
__device__ int   g_deg_in [RR*NN];
__device__ float g_rno[RR*NN];                  // rsqrt(max(deg_out,1))
__device__ float g_rni[RR*NN];                  // rsqrt(max(deg_in,1))
__device__ int   g_rowptr[RR*(NN+1)];
__device__ int   g_cursor[RR*NN];
__device__ int   g_csrc[(size_t)RR*EE];         // 16 MB CSR (by dst) source indices
__device__ float g_hg[GG*DHH];
__device__ int   g_gstart[GG+1];

// ---------------- preprocessing ----------------
__global__ void zero_deg_k() {
    int i = blockIdx.x * blockDim.x + threadIdx.x;
    if (i < RR*NN) { g_deg_out[i] = 0; g_deg_in[i] = 0; }
}

__global__ void count_deg_k(const int* __restrict__ edges) {
    int i = blockIdx.x * blockDim.x + threadIdx.x;
    if (i >= RR*EE) return;
    int r = i / EE, e = i - r*EE;
    int src = edges[(size_t)r*2*EE + e];
    int dst = edges[(size_t)r*2*EE + EE + e];
    atomicAdd(&g_deg_out[r*NN + src], 1);
    atomicAdd(&g_deg_in [r*NN + dst], 1);
}

__global__ void rnorm_k() {
    int i = blockIdx.x * blockDim.x + threadIdx.x;
    if (i >= RR*NN) return;
    g_rno[i] = rsqrtf(fmaxf((float)g_deg_out[i], 1.0f));
    g_rni[i] = rsqrtf(fmaxf((float)g_deg_in [i], 1.0f));
}

// exclusive scan of deg_in -> rowptr (+ cursor copy). One block per relation.
__global__ void scan_k() {
    __shared__ int sh[1024];
    int r = blockIdx.x, t = threadIdx.x;
    const int CH = (NN + 1023) / 1024;
    int b = t * CH; if (b > NN) b = NN;
    int e = b + CH; if (e > NN) e = NN;
    int s = 0;
    for (int i = b; i < e; i++) s += g_deg_in[r*NN + i];
    sh[t] = s;
    __syncthreads();
    for (int off = 1; off < 1024; off <<= 1) {
        int v = (t >= off) ? sh[t - off] : 0;
        __syncthreads();
        sh[t] += v;
        __syncthreads();
    }
    int run = sh[t] - s;   // exclusive prefix
    for (int i = b; i < e; i++) {
        g_rowptr[r*(NN+1) + i] = run;
        g_cursor[r*NN + i]     = run;
        run += g_deg_in[r*NN + i];
    }
    if (t == 1023) g_rowptr[r*(NN+1) + NN] = sh[1023];
}

__global__ void fill_k(const int* __restrict__ edges) {
    int i = blockIdx.x * blockDim.x + threadIdx.x;
    if (i >= RR*EE) return;
    int r = i / EE, e = i - r*EE;
    int src = edges[(size_t)r*2*EE + e];
    int dst = edges[(size_t)r*2*EE + EE + e];
    int pos = atomicAdd(&g_cursor[r*NN + dst], 1);
    g_csrc[(size_t)r*EE + pos] = src;
}

// ---------------- aggregation: one warp per (relation, dst) ----------------
// g_agg[n, r*128 + j] = rni[r,n] * sum_{s in N_r(n)} rno[r,s] * hin[s, j]
__global__ void __launch_bounds__(256) agg_k(const float* __restrict__ ext, int sel) {
    const float* hin = (sel < 0) ? ext : (sel == 0 ? g_h0 : g_h1);
    int w = (blockIdx.x * blockDim.x + threadIdx.x) >> 5;
    if (w >= RR*NN) return;
    int lane = threadIdx.x & 31;
    int r = w / NN, n = w - r*NN;
    int e0 = g_rowptr[r*(NN+1) + n];
    int e1 = g_rowptr[r*(NN+1) + n + 1];
    const int*   cs  = g_csrc + (size_t)r*EE;
    const float* rno = g_rno + r*NN;
    float4 acc = make_float4(0.f, 0.f, 0.f, 0.f);
    for (int e = e0; e < e1; e++) {
        int s = __ldg(cs + e);
        float wgt = __ldg(rno + s);
        float4 v = *(const float4*)(hin + (size_t)s*DHH + (lane << 2));
        acc.x = fmaf(wgt, v.x, acc.x);
        acc.y = fmaf(wgt, v.y, acc.y);
        acc.z = fmaf(wgt, v.z, acc.z);
        acc.w = fmaf(wgt, v.w, acc.w);
    }
    float ri = g_rni[r*NN + n];
    float4 o = make_float4(ri*acc.x, ri*acc.y, ri*acc.z, ri*acc.w);
    *(float4*)(g_agg + (size_t)n*KK + r*DHH + (lane << 2)) = o;
}

// ---------------- GEMM + bias + relu: [NN,512] @ [512,128] ----------------
__global__ void __launch_bounds__(256) gemm_relu_k(const float* __restrict__ W,
                                                   const float* __restrict__ Bv,
                                                   int outsel) {
    float* O = outsel ? g_h1 : g_h0;
    const float* A = g_agg;
    __shared__ float As[16][132];
    __shared__ float Bs[16][128];
    int tid = threadIdx.x;
    int rb = blockIdx.x * 128;
    int row0 = (tid >> 4) * 8;
    int col0 = (tid & 15) * 8;
    float acc[8][8];
    #pragma unroll
    for (int i = 0; i < 8; i++)
        #pragma unroll
        for (int j = 0; j < 8; j++) acc[i][j] = 0.f;

    for (int kt = 0; kt < 32; kt++) {
        int k0 = kt * 16;
        #pragma unroll
        for (int p = 0; p < 2; p++) {
            int f = tid + p*256;
            int row = f >> 2;
            int g4 = (f & 3) << 2;
            int gr = rb + row;
            float4 v = make_float4(0.f, 0.f, 0.f, 0.f);
            if (gr < NN) v = *(const float4*)(A + (size_t)gr*KK + k0 + g4);
            As[g4+0][row] = v.x; As[g4+1][row] = v.y;
            As[g4+2][row] = v.z; As[g4+3][row] = v.w;
        }
        #pragma unroll
        for (int p = 0; p < 2; p++) {
            int f = tid + p*256;
            int rw = f >> 5;
            int c = (f & 31) << 2;
            *(float4*)&Bs[rw][c] = *(const float4*)(W + (size_t)(k0 + rw)*DHH + c);
        }
        __syncthreads();
        #pragma unroll
        for (int k = 0; k < 16; k++) {
            float a[8], bb[8];
            *(float4*)(a)     = *(float4*)&As[k][row0];
            *(float4*)(a + 4) = *(float4*)&As[k][row0 + 4];
            *(float4*)(bb)     = *(float4*)&Bs[k][col0];
            *(float4*)(bb + 4) = *(float4*)&Bs[k][col0 + 4];
            #pragma unroll
            for (int i = 0; i < 8; i++)
                #pragma unroll
                for (int j = 0; j < 8; j++)
                    acc[i][j] = fmaf(a[i], bb[j], acc[i][j]);
        }
        __syncthreads();
    }

    float bias[8];
    #pragma unroll
    for (int j = 0; j < 8; j++) {
        float s = 0.f;
        #pragma unroll
        for (int r = 0; r < RR; r++) s += Bv[r*DHH + col0 + j];
        bias[j] = s;
    }
    #pragma unroll
    for (int i = 0; i < 8; i++) {
        int gr = rb + row0 + i;
        if (gr < NN) {
            float4 o0, o1;
            o0.x = fmaxf(acc[i][0] + bias[0], 0.f);
            o0.y = fmaxf(acc[i][1] + bias[1], 0.f);
            o0.z = fmaxf(acc[i][2] + bias[2], 0.f);
            o0.w = fmaxf(acc[i][3] + bias[3], 0.f);
            o1.x = fmaxf(acc[i][4] + bias[4], 0.f);
            o1.y = fmaxf(acc[i][5] + bias[5], 0.f);
            o1.z = fmaxf(acc[i][6] + bias[6], 0.f);
            o1.w = fmaxf(acc[i][7] + bias[7], 0.f);
            *(float4*)(O + (size_t)gr*DHH + col0)     = o0;
            *(float4*)(O + (size_t)gr*DHH + col0 + 4) = o1;
        }
    }
}

// ---------------- pooling + classifier ----------------
__global__ void bounds_k(const int* __restrict__ gid) {
    int i = blockIdx.x * blockDim.x + threadIdx.x;
    if (i > NN) return;
    int cur  = (i < NN) ? gid[i]   : GG;
    int prev = (i == 0) ? -1       : gid[i-1];
    for (int g = prev + 1; g <= cur; g++) g_gstart[g] = i;
}

__global__ void pool_k() {
    int g = blockIdx.x, j = threadIdx.x;
    int a = g_gstart[g], b = g_gstart[g+1];
    float s = 0.f;
    for (int n = a; n < b; n++) s += g_h0[(size_t)n*DHH + j];
    float c = fmaxf((float)(b - a), 1.0f);
    g_hg[g*DHH + j] = s / c;
}

__global__ void cls_k(const float* __restrict__ Wc, const float* __restrict__ bc,
                      float* __restrict__ out) {
    int idx = blockIdx.x * blockDim.x + threadIdx.x;
    if (idx >= GG*NCC) return;
    int g = idx / NCC, c = idx - g*NCC;
    float s = bc[c];
    #pragma unroll 8
    for (int k = 0; k < DHH; k++)
        s = fmaf(g_hg[g*DHH + k], Wc[k*NCC + c], s);
    out[idx] = s;
}

// ---------------- launch ----------------
extern "C" void kernel_launch(void* const* d_in, const int* in_sizes, int n_in,
                              void* d_out, int out_size) {
    const float* features = (const float*)d_in[0];
    const int*   edges    = (const int*)  d_in[1];
    const int*   gids     = (const int*)  d_in[2];
    const float* W0       = (const float*)d_in[3];
    const float* b0       = (const float*)d_in[4];
    const float* Wl       = (const float*)d_in[5];
    const float* bl       = (const float*)d_in[6];
    const float* Wc       = (const float*)d_in[7];
    const float* bc       = (const float*)d_in[8];
    float* out = (float*)d_out;

    // structure preprocessing (reused by all 3 layers)
    zero_deg_k <<<(RR*NN + 255)/256, 256>>>();
    count_deg_k<<<(RR*EE + 255)/256, 256>>>(edges);
    rnorm_k    <<<(RR*NN + 255)/256, 256>>>();
    scan_k     <<<RR, 1024>>>();
    fill_k     <<<(RR*EE + 255)/256, 256>>>(edges);

    const int AGG_BLOCKS  = (RR*NN*32 + 255)/256;   // one warp per (r, dst)
    const int GEMM_BLOCKS = (NN + 127)/128;

    // layer 0: features -> h0
    agg_k      <<<AGG_BLOCKS, 256>>>(features, -1);
    gemm_relu_k<<<GEMM_BLOCKS, 256>>>(W0, b0, 0);
    // layer 1: h0 -> h1
    agg_k      <<<AGG_BLOCKS, 256>>>(nullptr, 0);
    gemm_relu_k<<<GEMM_BLOCKS, 256>>>(Wl, bl, 1);
    // layer 2: h1 -> h0
    agg_k      <<<AGG_BLOCKS, 256>>>(nullptr, 1);
    gemm_relu_k<<<GEMM_BLOCKS, 256>>>(Wl + (size_t)RR*DHH*DHH, bl + RR*DHH, 0);

    // pooling + classifier
    bounds_k<<<(NN + 256)/256, 256>>>(gids);
    pool_k  <<<GG, DHH>>>();
    cls_k   <<<(GG*NCC + 255)/256, 256>>>(Wc, bc, out);
}

// round 2
// speedup vs baseline: 1.7016x; 1.7016x over previous
#include <cuda_runtime.h>
#include <cuda_bf16.h>

#define NN   100000
#define EE   1000000
#define RR   4
#define GG   256
#define DHH  128
#define NCC  10
#define KK   (RR*DHH)   // 512
#define SB   98         // scan blocks per relation: ceil(NN/1024)

// ---------------- scratch (device globals; no allocation allowed) ----------------
__device__ float g_h0[(size_t)NN*DHH];
__device__ float g_h1[(size_t)NN*DHH];
__device__ float g_agg[(size_t)NN*KK];
__device__ int   g_deg_out[RR*NN];
__device__ int   g_deg_in [RR*NN];
__device__ float g_rno[RR*NN];
__device__ float g_rni[RR*NN];
__device__ int   g_rowptr[RR*(NN+1)];
__device__ int   g_cursor[RR*NN];
__device__ int   g_csrc[(size_t)RR*EE];
__device__ float g_hg[GG*DHH];
__device__ int   g_gstart[GG+1];
__device__ int   g_bsum[RR*SB];

// ---------------- preprocessing ----------------
__global__ void zero_deg_k() {
    int i = blockIdx.x * blockDim.x + threadIdx.x;
    if (i < RR*NN) { g_deg_out[i] = 0; g_deg_in[i] = 0; }
}

__global__ void count_deg_k(const int* __restrict__ edges) {
    int i = blockIdx.x * blockDim.x + threadIdx.x;
    if (i >= RR*EE) return;
    int r = i / EE, e = i - r*EE;
    int src = edges[(size_t)r*2*EE + e];
    int dst = edges[(size_t)r*2*EE + EE + e];
    atomicAdd(&g_deg_out[r*NN + src], 1);
    atomicAdd(&g_deg_in [r*NN + dst], 1);
}

__global__ void rnorm_k() {
    int i = blockIdx.x * blockDim.x + threadIdx.x;
    if (i >= RR*NN) return;
    g_rno[i] = rsqrtf(fmaxf((float)g_deg_out[i], 1.0f));
    g_rni[i] = rsqrtf(fmaxf((float)g_deg_in [i], 1.0f));
}

// ---- parallel scan: phase 1 (block-local exclusive scan) ----
__global__ void scan1_k() {
    __shared__ int sh[1024];
    int r = blockIdx.y, b = blockIdx.x, t = threadIdx.x;
    int i = b * 1024 + t;
    int v = (i < NN) ? g_deg_in[r*NN + i] : 0;
    sh[t] = v;
    __syncthreads();
    #pragma unroll
    for (int off = 1; off < 1024; off <<= 1) {
        int x = (t >= off) ? sh[t - off] : 0;
        __syncthreads();
        sh[t] += x;
        __syncthreads();
    }
    int excl = sh[t] - v;   // block-local exclusive prefix
    if (i < NN) g_rowptr[r*(NN+1) + i] = excl;
    if (t == 1023) g_bsum[r*SB + b] = sh[1023];
}

// ---- phase 2: scan the block sums (tiny) ----
__global__ void scan2_k() {
    int r = threadIdx.x;
    if (r >= RR) return;
    int run = 0;
    for (int b = 0; b < SB; b++) {
        int v = g_bsum[r*SB + b];
        g_bsum[r*SB + b] = run;
        run += v;
    }
    g_rowptr[r*(NN+1) + NN] = run;
}

// ---- phase 3: add block offsets, produce cursor ----
__global__ void scan3_k() {
    int i = blockIdx.x * blockDim.x + threadIdx.x;
    if (i >= RR*NN) return;
    int r = i / NN, n = i - r*NN;
    int off = g_bsum[r*SB + (n >> 10)];
    int v = g_rowptr[r*(NN+1) + n] + off;
    g_rowptr[r*(NN+1) + n] = v;
    g_cursor[r*NN + n] = v;
}

__global__ void fill_k(const int* __restrict__ edges) {
    int i = blockIdx.x * blockDim.x + threadIdx.x;
    if (i >= RR*EE) return;
    int r = i / EE, e = i - r*EE;
    int src = edges[(size_t)r*2*EE + e];
    int dst = edges[(size_t)r*2*EE + EE + e];
    int pos = atomicAdd(&g_cursor[r*NN + dst], 1);
    g_csrc[(size_t)r*EE + pos] = src;
}

// ---------------- aggregation: one warp per (relation, dst) ----------------
__global__ void __launch_bounds__(256) agg_k(const float* __restrict__ ext, int sel) {
    const float* hin = (sel < 0) ? ext : (sel == 0 ? g_h0 : g_h1);
    int w = (blockIdx.x * blockDim.x + threadIdx.x) >> 5;
    if (w >= RR*NN) return;
    int lane = threadIdx.x & 31;
    int r = w / NN, n = w - r*NN;
    int e0 = g_rowptr[r*(NN+1) + n];
    int e1 = g_rowptr[r*(NN+1) + n + 1];
    const int*   cs  = g_csrc + (size_t)r*EE;
    const float* rno = g_rno + r*NN;
    float4 acc = make_float4(0.f, 0.f, 0.f, 0.f);
    for (int e = e0; e < e1; e++) {
        int s = __ldg(cs + e);
        float wgt = __ldg(rno + s);
        float4 v = *(const float4*)(hin + (size_t)s*DHH + (lane << 2));
        acc.x = fmaf(wgt, v.x, acc.x);
        acc.y = fmaf(wgt, v.y, acc.y);
        acc.z = fmaf(wgt, v.z, acc.z);
        acc.w = fmaf(wgt, v.w, acc.w);
    }
    float ri = g_rni[r*NN + n];
    float4 o = make_float4(ri*acc.x, ri*acc.y, ri*acc.z, ri*acc.w);
    *(float4*)(g_agg + (size_t)n*KK + r*DHH + (lane << 2)) = o;
}

// ---------------- tf32 tensor-core GEMM + bias + relu: [NN,512] @ [512,128] ----------------
__device__ __forceinline__ unsigned f2tf(float x) {
    unsigned y;
    asm("cvt.rna.tf32.f32 %0, %1;" : "=r"(y) : "f"(x));
    return y;
}

__device__ __forceinline__ void mma_tf32(float* c, const unsigned* a, const unsigned* b) {
    asm volatile(
        "mma.sync.aligned.m16n8k8.row.col.f32.tf32.tf32.f32 "
        "{%0,%1,%2,%3}, {%4,%5,%6,%7}, {%8,%9}, {%0,%1,%2,%3};"
        : "+f"(c[0]), "+f"(c[1]), "+f"(c[2]), "+f"(c[3])
        : "r"(a[0]), "r"(a[1]), "r"(a[2]), "r"(a[3]), "r"(b[0]), "r"(b[1]));
}

// BM=128, BN=128, BK=16, 256 threads (8 warps in 2x4), warp tile 64x32
__global__ void __launch_bounds__(256) gemm_tc_k(const float* __restrict__ W,
                                                 const float* __restrict__ Bv,
                                                 int outsel) {
    __shared__ unsigned As[2][128][20];   // stride 20: conflict-free frag reads
    __shared__ unsigned Bs[2][16][136];   // stride 136: conflict-free frag reads

    float* O = outsel ? g_h1 : g_h0;
    const float* A = g_agg;

    int tid = threadIdx.x;
    int rb = blockIdx.x * 128;
    int wid = tid >> 5, lane = tid & 31;
    int wm = wid & 1, wn = wid >> 1;      // warp grid 2(m) x 4(n)
    int g = lane >> 2, t = lane & 3;

    // global-load index precompute
    int arow[2], ac4[2], brw[2], bc4[2];
    #pragma unroll
    for (int p = 0; p < 2; p++) {
        int f = tid + p*256;
        arow[p] = f >> 2;  ac4[p] = (f & 3) << 2;
        brw[p]  = f >> 5;  bc4[p] = (f & 31) << 2;
    }

    unsigned areg[2][4], breg[2][4];
    float acc[4][4][4];
    #pragma unroll
    for (int mt = 0; mt < 4; mt++)
        #pragma unroll
        for (int nt = 0; nt < 4; nt++)
            #pragma unroll
            for (int j = 0; j < 4; j++) acc[mt][nt][j] = 0.f;

    // ---- load tile kt into regs ----
    auto loadg = [&](int kt) {
        int k0 = kt * 16;
        #pragma unroll
        for (int p = 0; p < 2; p++) {
            int gr = rb + arow[p];
            float4 v = make_float4(0.f,0.f,0.f,0.f);
            if (gr < NN) v = *(const float4*)(A + (size_t)gr*KK + k0 + ac4[p]);
            areg[p][0] = f2tf(v.x); areg[p][1] = f2tf(v.y);
            areg[p][2] = f2tf(v.z); areg[p][3] = f2tf(v.w);
            float4 w = *(const float4*)(W + (size_t)(k0 + brw[p])*DHH + bc4[p]);
            breg[p][0] = f2tf(w.x); breg[p][1] = f2tf(w.y);
            breg[p][2] = f2tf(w.z); breg[p][3] = f2tf(w.w);
        }
    };
    auto stores = [&](int buf) {
        #pragma unroll
        for (int p = 0; p < 2; p++) {
            *(uint4*)&As[buf][arow[p]][ac4[p]] =
                make_uint4(areg[p][0], areg[p][1], areg[p][2], areg[p][3]);
            *(uint4*)&Bs[buf][brw[p]][bc4[p]] =
                make_uint4(breg[p][0], breg[p][1], breg[p][2], breg[p][3]);
        }
    };

    loadg(0);
    stores(0);
    __syncthreads();

    for (int kt = 0; kt < 32; kt++) {
        int cur = kt & 1;
        if (kt < 31) loadg(kt + 1);

        #pragma unroll
        for (int ks = 0; ks < 2; ks++) {
            unsigned af[4][4], bf[4][2];
            int col0 = ks*8 + t;
            #pragma unroll
            for (int mt = 0; mt < 4; mt++) {
                int r0 = wm*64 + mt*16 + g;
                af[mt][0] = As[cur][r0    ][col0];
                af[mt][1] = As[cur][r0 + 8][col0];
                af[mt][2] = As[cur][r0    ][col0 + 4];
                af[mt][3] = As[cur][r0 + 8][col0 + 4];
            }
            int br = ks*8 + t;
            #pragma unroll
            for (int nt = 0; nt < 4; nt++) {
                int bcol = wn*32 + nt*8 + g;
                bf[nt][0] = Bs[cur][br    ][bcol];
                bf[nt][1] = Bs[cur][br + 4][bcol];
            }
            #pragma unroll
            for (int mt = 0; mt < 4; mt++)
                #pragma unroll
                for (int nt = 0; nt < 4; nt++)
                    mma_tf32(acc[mt][nt], af[mt], bf[nt]);
        }

        if (kt < 31) {
            __syncthreads();
            stores((kt + 1) & 1);
            __syncthreads();
        }
    }

    // bias (sum over 4 relations) + relu + store
    float bias[4][2];
    #pragma unroll
    for (int nt = 0; nt < 4; nt++) {
        int c0 = wn*32 + nt*8 + 2*t;
        #pragma unroll
        for (int j = 0; j < 2; j++) {
            float s = 0.f;
            #pragma unroll
            for (int r = 0; r < RR; r++) s += Bv[r*DHH + c0 + j];
            bias[nt][j] = s;
        }
    }
    #pragma unroll
    for (int mt = 0; mt < 4; mt++) {
        int r0 = rb + wm*64 + mt*16 + g;
        #pragma unroll
        for (int nt = 0; nt < 4; nt++) {
            int c0 = wn*32 + nt*8 + 2*t;
            if (r0 < NN) {
                float2 o;
                o.x = fmaxf(acc[mt][nt][0] + bias[nt][0], 0.f);
                o.y = fmaxf(acc[mt][nt][1] + bias[nt][1], 0.f);
                *(float2*)(O + (size_t)r0*DHH + c0) = o;
            }
            if (r0 + 8 < NN) {
                float2 o;
                o.x = fmaxf(acc[mt][nt][2] + bias[nt][0], 0.f);
                o.y = fmaxf(acc[mt][nt][3] + bias[nt][1], 0.f);
                *(float2*)(O + (size_t)(r0+8)*DHH + c0) = o;
            }
        }
    }
}

// ---------------- pooling + classifier ----------------
__global__ void bounds_k(const int* __restrict__ gid) {
    int i = blockIdx.x * blockDim.x + threadIdx.x;
    if (i > NN) return;
    int cur  = (i < NN) ? gid[i]   : GG;
    int prev = (i == 0) ? -1       : gid[i-1];
    for (int g = prev + 1; g <= cur; g++) g_gstart[g] = i;
}

__global__ void pool_k() {
    int g = blockIdx.x, j = threadIdx.x;
    int a = g_gstart[g], b = g_gstart[g+1];
    float s = 0.f;
    for (int n = a; n < b; n++) s += g_h0[(size_t)n*DHH + j];
    float c = fmaxf((float)(b - a), 1.0f);
    g_hg[g*DHH + j] = s / c;
}

__global__ void cls_k(const float* __restrict__ Wc, const float* __restrict__ bc,
                      float* __restrict__ out) {
    int idx = blockIdx.x * blockDim.x + threadIdx.x;
    if (idx >= GG*NCC) return;
    int g = idx / NCC, c = idx - g*NCC;
    float s = bc[c];
    #pragma unroll 8
    for (int k = 0; k < DHH; k++)
        s = fmaf(g_hg[g*DHH + k], Wc[k*NCC + c], s);
    out[idx] = s;
}

// ---------------- launch ----------------
extern "C" void kernel_launch(void* const* d_in, const int* in_sizes, int n_in,
                              void* d_out, int out_size) {
    const float* features = (const float*)d_in[0];
    const int*   edges    = (const int*)  d_in[1];
    const int*   gids     = (const int*)  d_in[2];
    const float* W0       = (const float*)d_in[3];
    const float* b0       = (const float*)d_in[4];
    const float* Wl       = (const float*)d_in[5];
    const float* bl       = (const float*)d_in[6];
    const float* Wc       = (const float*)d_in[7];
    const float* bc       = (const float*)d_in[8];
    float* out = (float*)d_out;

    // structure preprocessing (reused by all 3 layers)
    zero_deg_k <<<(RR*NN + 255)/256, 256>>>();
    count_deg_k<<<(RR*EE + 255)/256, 256>>>(edges);
    rnorm_k    <<<(RR*NN + 255)/256, 256>>>();
    scan1_k    <<<dim3(SB, RR), 1024>>>();
    scan2_k    <<<1, RR>>>();
    scan3_k    <<<(RR*NN + 255)/256, 256>>>();
    fill_k     <<<(RR*EE + 255)/256, 256>>>(edges);

    const int AGG_BLOCKS  = (RR*NN*32 + 255)/256;
    const int GEMM_BLOCKS = (NN + 127)/128;

    agg_k    <<<AGG_BLOCKS, 256>>>(features, -1);
    gemm_tc_k<<<GEMM_BLOCKS, 256>>>(W0, b0, 0);
    agg_k    <<<AGG_BLOCKS, 256>>>(nullptr, 0);
    gemm_tc_k<<<GEMM_BLOCKS, 256>>>(Wl, bl, 1);
    agg_k    <<<AGG_BLOCKS, 256>>>(nullptr, 1);
    gemm_tc_k<<<GEMM_BLOCKS, 256>>>(Wl + (size_t)RR*DHH*DHH, bl + RR*DHH, 0);

    bounds_k<<<(NN + 256)/256, 256>>>(gids);
    pool_k  <<<GG, DHH>>>();
    cls_k   <<<(GG*NCC + 255)/256, 256>>>(Wc, bc, out);
}

// round 3
// speedup vs baseline: 2.0741x; 1.2189x over previous
#include <cuda_runtime.h>
#include <cuda_fp16.h>

#define NN   100000
#define EE   1000000
#define RR   4
#define GG   256
#define DHH  128
#define NCC  10
#define KK   (RR*DHH)   // 512
#define SB   98         // ceil(NN/1024)

// ---------------- scratch ----------------
__device__ __half g_f16[(size_t)NN*DHH];    // fp16 features
__device__ __half g_h0h[(size_t)NN*DHH];    // ping
__device__ __half g_h1h[(size_t)NN*DHH];    // pong
__device__ __half g_aggh[(size_t)NN*KK];    // 102.4 MB concat aggregates (fp16)
__device__ unsigned g_wt[3*DHH*256];        // per-layer W, transposed+pair-packed half2
__device__ int   g_deg_out[RR*NN];
__device__ int   g_deg_in [RR*NN];
__device__ float g_rno[RR*NN];
__device__ float g_rni[RR*NN];
__device__ int   g_rowptr[RR*(NN+1)];
__device__ int   g_cursor[RR*NN];
__device__ int   g_csrc[(size_t)RR*EE];
__device__ float g_hg[GG*DHH];
__device__ int   g_gstart[GG+1];
__device__ int   g_bsum[RR*SB];

// ---------------- preprocessing ----------------
__global__ void zero_deg_k() {
    int i = blockIdx.x * blockDim.x + threadIdx.x;
    if (i < RR*NN) { g_deg_out[i] = 0; g_deg_in[i] = 0; }
}

__global__ void count_deg_k(const int* __restrict__ edges) {
    int i = blockIdx.x * blockDim.x + threadIdx.x;
    if (i >= RR*EE) return;
    int r = i / EE, e = i - r*EE;
    int src = edges[(size_t)r*2*EE + e];
    int dst = edges[(size_t)r*2*EE + EE + e];
    atomicAdd(&g_deg_out[r*NN + src], 1);
    atomicAdd(&g_deg_in [r*NN + dst], 1);
}

__global__ void rnorm_k() {
    int i = blockIdx.x * blockDim.x + threadIdx.x;
    if (i >= RR*NN) return;
    g_rno[i] = rsqrtf(fmaxf((float)g_deg_out[i], 1.0f));
    g_rni[i] = rsqrtf(fmaxf((float)g_deg_in [i], 1.0f));
}

__global__ void scan1_k() {
    __shared__ int sh[1024];
    int r = blockIdx.y, b = blockIdx.x, t = threadIdx.x;
    int i = b * 1024 + t;
    int v = (i < NN) ? g_deg_in[r*NN + i] : 0;
    sh[t] = v;
    __syncthreads();
    #pragma unroll
    for (int off = 1; off < 1024; off <<= 1) {
        int x = (t >= off) ? sh[t - off] : 0;
        __syncthreads();
        sh[t] += x;
        __syncthreads();
    }
    int excl = sh[t] - v;
    if (i < NN) g_rowptr[r*(NN+1) + i] = excl;
    if (t == 1023) g_bsum[r*SB + b] = sh[1023];
}

__global__ void scan2_k() {
    int r = threadIdx.x;
    if (r >= RR) return;
    int run = 0;
    for (int b = 0; b < SB; b++) {
        int v = g_bsum[r*SB + b];
        g_bsum[r*SB + b] = run;
        run += v;
    }
    g_rowptr[r*(NN+1) + NN] = run;
}

__global__ void scan3_k() {
    int i = blockIdx.x * blockDim.x + threadIdx.x;
    if (i >= RR*NN) return;
    int r = i / NN, n = i - r*NN;
    int off = g_bsum[r*SB + (n >> 10)];
    int v = g_rowptr[r*(NN+1) + n] + off;
    g_rowptr[r*(NN+1) + n] = v;
    g_cursor[r*NN + n] = v;
}

__global__ void fill_k(const int* __restrict__ edges) {
    int i = blockIdx.x * blockDim.x + threadIdx.x;
    if (i >= RR*EE) return;
    int r = i / EE, e = i - r*EE;
    int src = edges[(size_t)r*2*EE + e];
    int dst = edges[(size_t)r*2*EE + EE + e];
    int pos = atomicAdd(&g_cursor[r*NN + dst], 1);
    g_csrc[(size_t)r*EE + pos] = src;
}

// ---------------- conversions ----------------
__global__ void conv_feat_k(const float* __restrict__ f) {
    int i = blockIdx.x * blockDim.x + threadIdx.x;
    if (i >= NN*DHH/2) return;
    float2 v = ((const float2*)f)[i];
    ((__half2*)g_f16)[i] = __floats2half2_rn(v.x, v.y);
}

// g_wt[l][col][pair] = half2(W_l[2p][col], W_l[2p+1][col])
__global__ void conv_w_k(const float* __restrict__ W0, const float* __restrict__ Wl) {
    int i = blockIdx.x * blockDim.x + threadIdx.x;
    if (i >= 3*DHH*256) return;
    int l = i / (DHH*256);
    int rem = i - l*DHH*256;
    int col = rem >> 8;
    int p = rem & 255;
    const float* src = (l == 0) ? W0 : Wl + (size_t)(l-1)*KK*DHH;
    __half2 hv = __floats2half2_rn(src[(size_t)(2*p)*DHH + col],
                                   src[(size_t)(2*p+1)*DHH + col]);
    g_wt[i] = *reinterpret_cast<unsigned*>(&hv);
}

// ---------------- aggregation (fp16 gather, fp32 accumulate) ----------------
__global__ void __launch_bounds__(256) agg_k(int sel) {
    const __half* hin = (sel == 0) ? g_f16 : (sel == 1 ? g_h0h : g_h1h);
    int w = (blockIdx.x * blockDim.x + threadIdx.x) >> 5;
    if (w >= RR*NN) return;
    int lane = threadIdx.x & 31;
    int r = w / NN, n = w - r*NN;
    int e0 = g_rowptr[r*(NN+1) + n];
    int e1 = g_rowptr[r*(NN+1) + n + 1];
    const int*   cs  = g_csrc + (size_t)r*EE;
    const float* rno = g_rno + r*NN;
    float acc0 = 0.f, acc1 = 0.f, acc2 = 0.f, acc3 = 0.f;
    for (int e = e0; e < e1; e++) {
        int s = __ldg(cs + e);
        float wgt = __ldg(rno + s);
        uint2 v = *(const uint2*)(hin + (size_t)s*DHH + (lane << 2));
        float2 f01 = __half22float2(*reinterpret_cast<__half2*>(&v.x));
        float2 f23 = __half22float2(*reinterpret_cast<__half2*>(&v.y));
        acc0 = fmaf(wgt, f01.x, acc0);
        acc1 = fmaf(wgt, f01.y, acc1);
        acc2 = fmaf(wgt, f23.x, acc2);
        acc3 = fmaf(wgt, f23.y, acc3);
    }
    float ri = g_rni[r*NN + n];
    __half2 p01 = __floats2half2_rn(ri*acc0, ri*acc1);
    __half2 p23 = __floats2half2_rn(ri*acc2, ri*acc3);
    uint2 o;
    o.x = *reinterpret_cast<unsigned*>(&p01);
    o.y = *reinterpret_cast<unsigned*>(&p23);
    *(uint2*)(g_aggh + (size_t)n*KK + r*DHH + (lane << 2)) = o;
}

// ---------------- fp16 tensor-core GEMM + bias + relu ----------------
__device__ __forceinline__ void mma_f16(float* c, const unsigned* a, const unsigned* b) {
    asm volatile(
        "mma.sync.aligned.m16n8k16.row.col.f32.f16.f16.f32 "
        "{%0,%1,%2,%3}, {%4,%5,%6,%7}, {%8,%9}, {%0,%1,%2,%3};"
        : "+f"(c[0]), "+f"(c[1]), "+f"(c[2]), "+f"(c[3])
        : "r"(a[0]), "r"(a[1]), "r"(a[2]), "r"(a[3]), "r"(b[0]), "r"(b[1]));
}

// BM=128, BN=128, BK=16, 256 threads, 8 warps 2(m)x4(n), warp tile 64x32
__global__ void __launch_bounds__(256) gemm_tc_k(int layer, const float* __restrict__ Bv,
                                                 int outsel) {
    __shared__ unsigned As[2][128][12];   // [row][k-pair], stride 12: conflict-free
    __shared__ unsigned Bs[2][128][12];   // [col][k-pair]

    __half* O = (outsel == 0) ? g_h0h : g_h1h;
    const __half* A = g_aggh;
    const unsigned* Wt = g_wt + (size_t)layer*DHH*256;

    int tid = threadIdx.x;
    int rb = blockIdx.x * 128;
    int wid = tid >> 5, lane = tid & 31;
    int wm = wid & 1, wn = wid >> 1;
    int g = lane >> 2, t = lane & 3;

    uint2 areg[2], breg[2];
    float acc[4][4][4];
    #pragma unroll
    for (int mt = 0; mt < 4; mt++)
        #pragma unroll
        for (int nt = 0; nt < 4; nt++)
            #pragma unroll
            for (int j = 0; j < 4; j++) acc[mt][nt][j] = 0.f;

    auto loadg = [&](int kt) {
        int k0 = kt * 16;           // half offset in K
        #pragma unroll
        for (int p = 0; p < 2; p++) {
            int idx = tid + p*256;
            int row = idx >> 2, q = idx & 3;
            int gr = rb + row;
            areg[p] = (gr < NN) ? *(const uint2*)(A + (size_t)gr*KK + k0 + q*4)
                                : make_uint2(0u, 0u);
            breg[p] = *(const uint2*)(Wt + (size_t)row*256 + kt*8 + q*2);
        }
    };
    auto stores = [&](int buf) {
        #pragma unroll
        for (int p = 0; p < 2; p++) {
            int idx = tid + p*256;
            int row = idx >> 2, q = idx & 3;
            As[buf][row][2*q]   = areg[p].x;
            As[buf][row][2*q+1] = areg[p].y;
            Bs[buf][row][2*q]   = breg[p].x;
            Bs[buf][row][2*q+1] = breg[p].y;
        }
    };

    loadg(0);
    stores(0);
    __syncthreads();

    for (int kt = 0; kt < 32; kt++) {
        int cur = kt & 1;
        if (kt < 31) loadg(kt + 1);

        unsigned af[4][4], bf[4][2];
        #pragma unroll
        for (int mt = 0; mt < 4; mt++) {
            int r0 = wm*64 + mt*16 + g;
            af[mt][0] = As[cur][r0    ][t];
            af[mt][1] = As[cur][r0 + 8][t];
            af[mt][2] = As[cur][r0    ][t + 4];
            af[mt][3] = As[cur][r0 + 8][t + 4];
        }
        #pragma unroll
        for (int nt = 0; nt < 4; nt++) {
            int c0 = wn*32 + nt*8 + g;
            bf[nt][0] = Bs[cur][c0][t];
            bf[nt][1] = Bs[cur][c0][t + 4];
        }
        #pragma unroll
        for (int mt = 0; mt < 4; mt++)
            #pragma unroll
            for (int nt = 0; nt < 4; nt++)
                mma_f16(acc[mt][nt], af[mt], bf[nt]);

        if (kt < 31) {
            __syncthreads();
            stores((kt + 1) & 1);
            __syncthreads();
        }
    }

    float bias[4][2];
    #pragma unroll
    for (int nt = 0; nt < 4; nt++) {
        int c0 = wn*32 + nt*8 + 2*t;
        #pragma unroll
        for (int j = 0; j < 2; j++) {
            float s = 0.f;
            #pragma unroll
            for (int r = 0; r < RR; r++) s += Bv[r*DHH + c0 + j];
            bias[nt][j] = s;
        }
    }
    #pragma unroll
    for (int mt = 0; mt < 4; mt++) {
        int r0 = rb + wm*64 + mt*16 + g;
        #pragma unroll
        for (int nt = 0; nt < 4; nt++) {
            int c = wn*32 + nt*8 + 2*t;
            if (r0 < NN) {
                *(__half2*)(O + (size_t)r0*DHH + c) =
                    __floats2half2_rn(fmaxf(acc[mt][nt][0] + bias[nt][0], 0.f),
                                      fmaxf(acc[mt][nt][1] + bias[nt][1], 0.f));
            }
            if (r0 + 8 < NN) {
                *(__half2*)(O + (size_t)(r0+8)*DHH + c) =
                    __floats2half2_rn(fmaxf(acc[mt][nt][2] + bias[nt][0], 0.f),
                                      fmaxf(acc[mt][nt][3] + bias[nt][1], 0.f));
            }
        }
    }
}

// ---------------- pooling + classifier ----------------
__global__ void bounds_k(const int* __restrict__ gid) {
    int i = blockIdx.x * blockDim.x + threadIdx.x;
    if (i > NN) return;
    int cur  = (i < NN) ? gid[i] : GG;
    int prev = (i == 0) ? -1     : gid[i-1];
    for (int g = prev + 1; g <= cur; g++) g_gstart[g] = i;
}

__global__ void pool_k() {
    int g = blockIdx.x, j = threadIdx.x;
    int a = g_gstart[g], b = g_gstart[g+1];
    float s = 0.f;
    for (int n = a; n < b; n++) s += __half2float(g_h0h[(size_t)n*DHH + j]);
    float c = fmaxf((float)(b - a), 1.0f);
    g_hg[g*DHH + j] = s / c;
}

__global__ void cls_k(const float* __restrict__ Wc, const float* __restrict__ bc,
                      float* __restrict__ out) {
    int idx = blockIdx.x * blockDim.x + threadIdx.x;
    if (idx >= GG*NCC) return;
    int g = idx / NCC, c = idx - g*NCC;
    float s = bc[c];
    #pragma unroll 8
    for (int k = 0; k < DHH; k++)
        s = fmaf(g_hg[g*DHH + k], Wc[k*NCC + c], s);
    out[idx] = s;
}

// ---------------- launch ----------------
extern "C" void kernel_launch(void* const* d_in, const int* in_sizes, int n_in,
                              void* d_out, int out_size) {
    const float* features = (const float*)d_in[0];
    const int*   edges    = (const int*)  d_in[1];
    const int*   gids     = (const int*)  d_in[2];
    const float* W0       = (const float*)d_in[3];
    const float* b0       = (const float*)d_in[4];
    const float* Wl       = (const float*)d_in[5];
    const float* bl       = (const float*)d_in[6];
    const float* Wc       = (const float*)d_in[7];
    const float* bc       = (const float*)d_in[8];
    float* out = (float*)d_out;

    zero_deg_k <<<(RR*NN + 255)/256, 256>>>();
    count_deg_k<<<(RR*EE + 255)/256, 256>>>(edges);
    rnorm_k    <<<(RR*NN + 255)/256, 256>>>();
    scan1_k    <<<dim3(SB, RR), 1024>>>();
    scan2_k    <<<1, RR>>>();
    scan3_k    <<<(RR*NN + 255)/256, 256>>>();
    fill_k     <<<(RR*EE + 255)/256, 256>>>(edges);
    conv_feat_k<<<(NN*DHH/2 + 255)/256, 256>>>(features);
    conv_w_k   <<<(3*DHH*256 + 255)/256, 256>>>(W0, Wl);

    const int AGG_BLOCKS  = (RR*NN*32 + 255)/256;
    const int GEMM_BLOCKS = (NN + 127)/128;

    agg_k    <<<AGG_BLOCKS, 256>>>(0);           // features(fp16) -> agg
    gemm_tc_k<<<GEMM_BLOCKS, 256>>>(0, b0, 0);   // -> h0
    agg_k    <<<AGG_BLOCKS, 256>>>(1);           // h0 -> agg
    gemm_tc_k<<<GEMM_BLOCKS, 256>>>(1, bl, 1);   // -> h1
    agg_k    <<<AGG_BLOCKS, 256>>>(2);           // h1 -> agg
    gemm_tc_k<<<GEMM_BLOCKS, 256>>>(2, bl + RR*DHH, 0);  // -> h0

    bounds_k<<<(NN + 256)/256, 256>>>(gids);
    pool_k  <<<GG, DHH>>>();
    cls_k   <<<(GG*NCC + 255)/256, 256>>>(Wc, bc, out);
}